// round 11
// baseline (speedup 1.0000x reference)
#include <cuda_runtime.h>
#include <math.h>

// MT 1D forward + loss, fused single kernel. Output: [total, loss_rhoa, loss_phase].
//
// R11: 4-way warp-split chains, ONE block per SM (128 blocks = single wave),
// 4 warps per SMSP with per-SMSP fma-slot balance: each SMSP hosts one
// vector-role warp (deepest lv=75 layers applied to v0, ~12 fma/step) and
// three matrix-role warps (lm=60 layers each as 2x2 products, ~16 fma/step).
// Evidence R4..R10: wall = fixed ~5.5us bench floor + per-SMSP fma-class
// slots x 2cyc; extra warps (R9) and f32x2 packing (R10) were both neutral.
//
// Layer map on (U,V) (U=N+D, V=N-D, x=Z/Zj): M_j = [[1,-rE],[r,-E]],
// r=(g-1)/(g+1), g=sqrt(rho_j/rho_{j-1}), E=exp(-a)(cos a - i sin a),
// a=s*coef_j. Scale-invariant; renorm every 8 steps; outputs division-free.

#define MUF 1.25663706143591729e-6f   // 4*pi*1e-7
#define TWO_PI_F 6.2831853071795864f
#define RAD2DEG_F 57.295779513082321f

__device__ float2 g_part[256];
__device__ unsigned int g_ticket;     // zero-init; last block resets each launch

__device__ __forceinline__ float frcp_fast(float x) {
    float r; asm("rcp.approx.ftz.f32 %0,%1;" : "=f"(r) : "f"(x)); return r;
}

__device__ __forceinline__ void e_math(float coef, float s, float& er, float& ei)
{
    float a  = s * coef;
    float em = __expf(-a);
    float sa, ca;
    __sincosf(a, &sa, &ca);
    er = em * ca;                      // E = er - i*ei
    ei = em * sa;
}

__global__ __launch_bounds__(512, 1)
void mt_fused(const float* __restrict__ res,
              const float* __restrict__ thick,
              const float* __restrict__ freq,
              const float* __restrict__ orhoa,
              const float* __restrict__ ophase,
              float* __restrict__ out,
              int nz, int nf, float inv_nf)
{
    __shared__ float2 lay[512];        // (coef_j, r_j), deepest layer first
    __shared__ float  pmat[3][4][32][9];  // [role-1][group][lane][8(+pad)]
    __shared__ float  sc_x0, sc_lrho0;
    __shared__ float2 red[16];
    __shared__ int    is_last;

    const int nl  = nz - 1;
    const int tid = threadIdx.x;

    for (int i = tid; i < nl; i += blockDim.x) {
        int   j   = nl - 1 - i;                    // deepest first
        float rho = res[j];
        float t   = thick[j];
        float g   = (j >= 1) ? sqrtf(rho / res[j - 1]) : 1.0f;
        lay[i] = make_float2(t * sqrtf(2.0f * MUF / rho),
                             (g - 1.0f) / (g + 1.0f));
    }
    if (tid == 0) {
        sc_x0    = sqrtf(res[nz - 1] / res[nz - 2]);
        sc_lrho0 = log10f(res[0]);
    }
    __syncthreads();

    const int wid  = tid >> 5;         // 0..15
    const int lane = tid & 31;
    const int grp  = wid & 3;          // freq group within block (also SMSP id)
    const int role = wid >> 2;         // 0 = vector, 1..3 = matrix
    const int fq   = blockIdx.x * 128 + grp * 32 + lane;

    // segment split: lv + 3*lm = nl, fma-slot balanced (lv=75, lm=60 @ nl=255)
    const int lm = (nl * 4) / 17;
    const int lv = nl - 3 * lm;

    float lr = 0.0f, lp = 0.0f;

    float omega = TWO_PI_F * __ldg(&freq[min(fq, nf - 1)]);
    float s     = sqrtf(omega);

    if (role == 0) {
        // ---- vector warp: deepest lv layers applied to v0 ----
        float x0 = sc_x0;
        float Ur = x0 + 1.0f, Ui = 0.0f;
        float Vr = x0 - 1.0f, Vi = 0.0f;

        int i = 0;
        for (; i + 8 <= lv; i += 8) {
            #pragma unroll
            for (int u = 0; u < 8; ++u) {
                float2 L = lay[i + u];
                float er, ei;
                e_math(L.x, s, er, ei);
                float wr = er * Vr + ei * Vi;      // w = E*V
                float wi = er * Vi - ei * Vr;
                float r  = L.y;
                float nUr = fmaf(-r, wr, Ur);
                float nUi = fmaf(-r, wi, Ui);
                float nVr = fmaf( r, Ur, -wr);
                float nVi = fmaf( r, Ui, -wi);
                Ur = nUr; Ui = nUi; Vr = nVr; Vi = nVi;
            }
            float m = frcp_fast(fabsf(Ur) + fabsf(Ui));
            Ur *= m; Ui *= m; Vr *= m; Vi *= m;
        }
        for (; i < lv; ++i) {
            float2 L = lay[i];
            float er, ei;
            e_math(L.x, s, er, ei);
            float wr = er * Vr + ei * Vi;
            float wi = er * Vi - ei * Vr;
            float r  = L.y;
            float nUr = fmaf(-r, wr, Ur);
            float nUi = fmaf(-r, wi, Ui);
            float nVr = fmaf( r, Ur, -wr);
            float nVi = fmaf( r, Ui, -wi);
            Ur = nUr; Ui = nUi; Vr = nVr; Vi = nVi;
        }

        __syncthreads();               // wait for matrix warps' pmat writes

        #pragma unroll
        for (int q = 0; q < 3; ++q) {
            const float* P = pmat[q][grp][lane];
            float p00r = P[0], p00i = P[1], p01r = P[2], p01i = P[3];
            float p10r = P[4], p10i = P[5], p11r = P[6], p11i = P[7];
            float nUr = p00r * Ur - p00i * Ui + p01r * Vr - p01i * Vi;
            float nUi = p00r * Ui + p00i * Ur + p01r * Vi + p01i * Vr;
            float nVr = p10r * Ur - p10i * Ui + p11r * Vr - p11i * Vi;
            float nVi = p10r * Ui + p10i * Ur + p11r * Vi + p11i * Vr;
            float m = frcp_fast(fabsf(nUr) + fabsf(nUi));
            Ur = nUr * m; Ui = nUi * m; Vr = nVr * m; Vi = nVi * m;
        }

        if (fq < nf) {
            float Nr = Ur + Vr, Ni = Ui + Vi;
            float Dr = Ur - Vr, Di = Ui - Vi;
            float n2 = fmaxf(Nr * Nr + Ni * Ni, 1e-30f);
            float d2 = fmaxf(Dr * Dr + Di * Di, 1e-30f);
            float A  = Nr * Dr + Ni * Di;
            float B  = Ni * Dr - Nr * Di;
            float e1 = sc_lrho0 + log10f(n2) - log10f(d2) - log10f(__ldg(&orhoa[fq]));
            float ph = atan2f(A + B, A - B) * RAD2DEG_F;
            float e2 = ph - __ldg(&ophase[fq]);
            lr = e1 * e1;
            lp = e2 * e2;
        }
    } else {
        // ---- matrix warp: layers [lv+(role-1)*lm, lv+role*lm) ----
        const int start = lv + (role - 1) * lm;
        const int end   = start + lm;

        float p00r = 1.0f, p00i = 0.0f, p01r = 0.0f, p01i = 0.0f;
        float p10r = 0.0f, p10i = 0.0f, p11r = 1.0f, p11i = 0.0f;

        int i = start;
        for (; i + 8 <= end; i += 8) {
            #pragma unroll
            for (int u = 0; u < 8; ++u) {
                float2 L = lay[i + u];
                float er, ei;
                e_math(L.x, s, er, ei);
                float r = L.y;
                float Xr = er * p10r + ei * p10i;  // X = E*p10 (E = er - i*ei)
                float Xi = er * p10i - ei * p10r;
                float Yr = er * p11r + ei * p11i;  // Y = E*p11
                float Yi = er * p11i - ei * p11r;
                float n00r = fmaf(-r, Xr, p00r);
                float n00i = fmaf(-r, Xi, p00i);
                float n01r = fmaf(-r, Yr, p01r);
                float n01i = fmaf(-r, Yi, p01i);
                float n10r = fmaf( r, p00r, -Xr);
                float n10i = fmaf( r, p00i, -Xi);
                float n11r = fmaf( r, p01r, -Yr);
                float n11i = fmaf( r, p01i, -Yi);
                p00r = n00r; p00i = n00i; p01r = n01r; p01i = n01i;
                p10r = n10r; p10i = n10i; p11r = n11r; p11i = n11i;
            }
            float m = frcp_fast(fabsf(p00r) + fabsf(p00i)
                              + fabsf(p10r) + fabsf(p10i));
            p00r *= m; p00i *= m; p01r *= m; p01i *= m;
            p10r *= m; p10i *= m; p11r *= m; p11i *= m;
        }
        for (; i < end; ++i) {
            float2 L = lay[i];
            float er, ei;
            e_math(L.x, s, er, ei);
            float r = L.y;
            float Xr = er * p10r + ei * p10i;
            float Xi = er * p10i - ei * p10r;
            float Yr = er * p11r + ei * p11i;
            float Yi = er * p11i - ei * p11r;
            float n00r = fmaf(-r, Xr, p00r);
            float n00i = fmaf(-r, Xi, p00i);
            float n01r = fmaf(-r, Yr, p01r);
            float n01i = fmaf(-r, Yi, p01i);
            float n10r = fmaf( r, p00r, -Xr);
            float n10i = fmaf( r, p00i, -Xi);
            float n11r = fmaf( r, p01r, -Yr);
            float n11i = fmaf( r, p01i, -Yi);
            p00r = n00r; p00i = n00i; p01r = n01r; p01i = n01i;
            p10r = n10r; p10i = n10i; p11r = n11r; p11i = n11i;
        }

        float* P = pmat[role - 1][grp][lane];
        P[0] = p00r; P[1] = p00i; P[2] = p01r; P[3] = p01i;
        P[4] = p10r; P[5] = p10i; P[6] = p11r; P[7] = p11i;
        __syncthreads();               // publish to vector warps
    }

    // deterministic block reduction (16 warps; only vector warps nonzero)
    const unsigned FULL = 0xffffffffu;
    #pragma unroll
    for (int o = 16; o > 0; o >>= 1) {
        lr += __shfl_down_sync(FULL, lr, o);
        lp += __shfl_down_sync(FULL, lp, o);
    }
    if (lane == 0) red[wid] = make_float2(lr, lp);
    __syncthreads();
    if (tid == 0) {
        float slr = 0.0f, slp = 0.0f;
        #pragma unroll
        for (int w = 0; w < 16; ++w) { slr += red[w].x; slp += red[w].y; }
        g_part[blockIdx.x] = make_float2(slr, slp);
        __threadfence();
        unsigned t = atomicAdd(&g_ticket, 1u);
        is_last = (t == gridDim.x - 1) ? 1 : 0;
    }
    __syncthreads();

    if (is_last) {
        __threadfence();
        float flr = 0.0f, flp = 0.0f;
        if (tid < 32) {
            for (int i = tid; i < (int)gridDim.x; i += 32) {
                volatile float* vp = (volatile float*)&g_part[i];
                flr += vp[0];
                flp += vp[1];
            }
            #pragma unroll
            for (int o = 16; o > 0; o >>= 1) {
                flr += __shfl_down_sync(FULL, flr, o);
                flp += __shfl_down_sync(FULL, flp, o);
            }
            if (tid == 0) {
                float mlr = flr * inv_nf;
                float mlp = flp * inv_nf;
                out[0] = mlr + 10.0f * mlp;   // LAMBDA_RHOA=1, LAMBDA_PHASE=10
                out[1] = mlr;
                out[2] = mlp;
                g_ticket = 0;                 // reset for next graph replay
            }
        }
    }
}

extern "C" void kernel_launch(void* const* d_in, const int* in_sizes, int n_in,
                              void* d_out, int out_size)
{
    const float* res = (const float*)d_in[0];
    const float* th  = (const float*)d_in[1];
    const float* fr  = (const float*)d_in[2];
    const float* orh = (const float*)d_in[3];
    const float* oph = (const float*)d_in[4];
    int nz = in_sizes[0];
    int nf = in_sizes[2];

    const int threads = 512;               // 16 warps: 4 vector + 12 matrix
    int blocks = (nf + 127) / 128;         // 128 blocks = single wave on 148 SMs
    if (blocks > 256) blocks = 256;

    mt_fused<<<blocks, threads>>>(res, th, fr, orh, oph,
                                  (float*)d_out, nz, nf, 1.0f / (float)nf);
}

// round 12
// speedup vs baseline: 1.0155x; 1.0155x over previous
#include <cuda_runtime.h>
#include <math.h>

// MT 1D forward + loss, fused. Output: [total, loss_rhoa, loss_phase].
//
// R12: k=4 chain split, 512 blocks x 128 threads (1 freq-group of 32 freqs
// per block; warps: 1 vector + 3 matrix). Rationale from R4-R11 data:
// wall ~ max(per-SMSP fma-slots x2, MUFU, latency). k=4 at 512 small blocks
// gives (a) avg 17.2 fma-slots/layer (vs 18.8 at R9's k=8), (b) ~3.46
// blocks/SM over ALL 148 SMs (vs 128 SMs in R7/R11), (c) ~3.5 warps/SMSP
// for latency hiding (vs R7's 1.7 @ issue=40%). Segments instr-balanced:
// 17*lv = 26*lm -> lv=87, lm=56 (nl=255).
//
// Layer map on (U,V): M_j = [[1,-rE],[r,-E]], r=(g-1)/(g+1),
// E = exp(-a)(cos a - i sin a), a = s*coef_j. Scale-invariant, renorm/8.

#define MUF 1.25663706143591729e-6f   // 4*pi*1e-7
#define TWO_PI_F 6.2831853071795864f
#define RAD2DEG_F 57.295779513082321f

__device__ float2 g_part[512];
__device__ unsigned int g_ticket;     // zero-init; last block resets each launch

__device__ __forceinline__ float frcp_fast(float x) {
    float r; asm("rcp.approx.ftz.f32 %0,%1;" : "=f"(r) : "f"(x)); return r;
}

__device__ __forceinline__ void e_math(float coef, float s, float& er, float& ei)
{
    float a  = s * coef;
    float em = __expf(-a);
    float sa, ca;
    __sincosf(a, &sa, &ca);
    er = em * ca;                      // E = er - i*ei
    ei = em * sa;
}

__global__ __launch_bounds__(128, 8)
void mt_fused(const float* __restrict__ res,
              const float* __restrict__ thick,
              const float* __restrict__ freq,
              const float* __restrict__ orhoa,
              const float* __restrict__ ophase,
              float* __restrict__ out,
              int nz, int nf, float inv_nf)
{
    __shared__ float2 lay[512];        // (coef_j, r_j), deepest layer first
    __shared__ float  pmat[3][32][9];  // matrix-warp products (+pad)
    __shared__ float  sc_x0, sc_lrho0;
    __shared__ float2 red[4];
    __shared__ int    is_last;

    const int nl  = nz - 1;
    const int tid = threadIdx.x;

    for (int i = tid; i < nl; i += blockDim.x) {
        int   j   = nl - 1 - i;                    // deepest first
        float rho = res[j];
        float t   = thick[j];
        float g   = (j >= 1) ? sqrtf(rho / res[j - 1]) : 1.0f;
        lay[i] = make_float2(t * sqrtf(2.0f * MUF / rho),
                             (g - 1.0f) / (g + 1.0f));
    }
    if (tid == 0) {
        sc_x0    = sqrtf(res[nz - 1] / res[nz - 2]);
        sc_lrho0 = log10f(res[0]);
    }
    __syncthreads();

    const int wid  = tid >> 5;         // 0 = vector, 1..3 = matrix
    const int lane = tid & 31;
    const int fq   = blockIdx.x * 32 + lane;

    // instr-balanced split: 17*lv = 26*lm, lv + 3*lm = nl -> lm = 17nl/77
    const int lm = (17 * nl) / 77;                 // 56 for nl=255
    const int lv = nl - 3 * lm;                    // 87 for nl=255

    float lr = 0.0f, lp = 0.0f;

    float omega = TWO_PI_F * __ldg(&freq[min(fq, nf - 1)]);
    float s     = sqrtf(omega);

    if (wid == 0) {
        // ---- vector warp: deepest lv layers applied to v0 ----
        float x0 = sc_x0;
        float Ur = x0 + 1.0f, Ui = 0.0f;
        float Vr = x0 - 1.0f, Vi = 0.0f;

        int i = 0;
        for (; i + 8 <= lv; i += 8) {
            #pragma unroll
            for (int u = 0; u < 8; ++u) {
                float2 L = lay[i + u];
                float er, ei;
                e_math(L.x, s, er, ei);
                float wr = er * Vr + ei * Vi;      // w = E*V
                float wi = er * Vi - ei * Vr;
                float r  = L.y;
                float nUr = fmaf(-r, wr, Ur);
                float nUi = fmaf(-r, wi, Ui);
                float nVr = fmaf( r, Ur, -wr);
                float nVi = fmaf( r, Ui, -wi);
                Ur = nUr; Ui = nUi; Vr = nVr; Vi = nVi;
            }
            float m = frcp_fast(fabsf(Ur) + fabsf(Ui));
            Ur *= m; Ui *= m; Vr *= m; Vi *= m;
        }
        for (; i < lv; ++i) {
            float2 L = lay[i];
            float er, ei;
            e_math(L.x, s, er, ei);
            float wr = er * Vr + ei * Vi;
            float wi = er * Vi - ei * Vr;
            float r  = L.y;
            float nUr = fmaf(-r, wr, Ur);
            float nUi = fmaf(-r, wi, Ui);
            float nVr = fmaf( r, Ur, -wr);
            float nVi = fmaf( r, Ui, -wi);
            Ur = nUr; Ui = nUi; Vr = nVr; Vi = nVi;
        }

        __syncthreads();               // wait for matrix warps' pmat writes

        #pragma unroll
        for (int q = 0; q < 3; ++q) {
            const float* P = pmat[q][lane];
            float p00r = P[0], p00i = P[1], p01r = P[2], p01i = P[3];
            float p10r = P[4], p10i = P[5], p11r = P[6], p11i = P[7];
            float nUr = p00r * Ur - p00i * Ui + p01r * Vr - p01i * Vi;
            float nUi = p00r * Ui + p00i * Ur + p01r * Vi + p01i * Vr;
            float nVr = p10r * Ur - p10i * Ui + p11r * Vr - p11i * Vi;
            float nVi = p10r * Ui + p10i * Ur + p11r * Vi + p11i * Vr;
            float m = frcp_fast(fabsf(nUr) + fabsf(nUi));
            Ur = nUr * m; Ui = nUi * m; Vr = nVr * m; Vi = nVi * m;
        }

        if (fq < nf) {
            float Nr = Ur + Vr, Ni = Ui + Vi;
            float Dr = Ur - Vr, Di = Ui - Vi;
            float n2 = fmaxf(Nr * Nr + Ni * Ni, 1e-30f);
            float d2 = fmaxf(Dr * Dr + Di * Di, 1e-30f);
            float A  = Nr * Dr + Ni * Di;
            float B  = Ni * Dr - Nr * Di;
            float e1 = sc_lrho0 + log10f(n2) - log10f(d2) - log10f(__ldg(&orhoa[fq]));
            float ph = atan2f(A + B, A - B) * RAD2DEG_F;
            float e2 = ph - __ldg(&ophase[fq]);
            lr = e1 * e1;
            lp = e2 * e2;
        }
    } else {
        // ---- matrix warp wid: layers [lv+(wid-1)*lm, lv+wid*lm) ----
        const int start = lv + (wid - 1) * lm;
        const int end   = start + lm;

        float p00r = 1.0f, p00i = 0.0f, p01r = 0.0f, p01i = 0.0f;
        float p10r = 0.0f, p10i = 0.0f, p11r = 1.0f, p11i = 0.0f;

        int i = start;
        for (; i + 8 <= end; i += 8) {
            #pragma unroll
            for (int u = 0; u < 8; ++u) {
                float2 L = lay[i + u];
                float er, ei;
                e_math(L.x, s, er, ei);
                float r = L.y;
                float Xr = er * p10r + ei * p10i;  // X = E*p10 (E = er - i*ei)
                float Xi = er * p10i - ei * p10r;
                float Yr = er * p11r + ei * p11i;  // Y = E*p11
                float Yi = er * p11i - ei * p11r;
                float n00r = fmaf(-r, Xr, p00r);
                float n00i = fmaf(-r, Xi, p00i);
                float n01r = fmaf(-r, Yr, p01r);
                float n01i = fmaf(-r, Yi, p01i);
                float n10r = fmaf( r, p00r, -Xr);
                float n10i = fmaf( r, p00i, -Xi);
                float n11r = fmaf( r, p01r, -Yr);
                float n11i = fmaf( r, p01i, -Yi);
                p00r = n00r; p00i = n00i; p01r = n01r; p01i = n01i;
                p10r = n10r; p10i = n10i; p11r = n11r; p11i = n11i;
            }
            float m = frcp_fast(fabsf(p00r) + fabsf(p00i)
                              + fabsf(p10r) + fabsf(p10i));
            p00r *= m; p00i *= m; p01r *= m; p01i *= m;
            p10r *= m; p10i *= m; p11r *= m; p11i *= m;
        }
        for (; i < end; ++i) {
            float2 L = lay[i];
            float er, ei;
            e_math(L.x, s, er, ei);
            float r = L.y;
            float Xr = er * p10r + ei * p10i;
            float Xi = er * p10i - ei * p10r;
            float Yr = er * p11r + ei * p11i;
            float Yi = er * p11i - ei * p11r;
            float n00r = fmaf(-r, Xr, p00r);
            float n00i = fmaf(-r, Xi, p00i);
            float n01r = fmaf(-r, Yr, p01r);
            float n01i = fmaf(-r, Yi, p01i);
            float n10r = fmaf( r, p00r, -Xr);
            float n10i = fmaf( r, p00i, -Xi);
            float n11r = fmaf( r, p01r, -Yr);
            float n11i = fmaf( r, p01i, -Yi);
            p00r = n00r; p00i = n00i; p01r = n01r; p01i = n01i;
            p10r = n10r; p10i = n10i; p11r = n11r; p11i = n11i;
        }

        float* P = pmat[wid - 1][lane];
        P[0] = p00r; P[1] = p00i; P[2] = p01r; P[3] = p01i;
        P[4] = p10r; P[5] = p10i; P[6] = p11r; P[7] = p11i;
        __syncthreads();               // publish to vector warp
    }

    // deterministic block reduction (4 warps; only warp 0 nonzero)
    const unsigned FULL = 0xffffffffu;
    #pragma unroll
    for (int o = 16; o > 0; o >>= 1) {
        lr += __shfl_down_sync(FULL, lr, o);
        lp += __shfl_down_sync(FULL, lp, o);
    }
    if (lane == 0) red[wid] = make_float2(lr, lp);
    __syncthreads();
    if (tid == 0) {
        float slr = red[0].x + red[1].x + red[2].x + red[3].x;
        float slp = red[0].y + red[1].y + red[2].y + red[3].y;
        g_part[blockIdx.x] = make_float2(slr, slp);
        __threadfence();
        unsigned t = atomicAdd(&g_ticket, 1u);
        is_last = (t == gridDim.x - 1) ? 1 : 0;
    }
    __syncthreads();

    if (is_last) {
        __threadfence();
        float flr = 0.0f, flp = 0.0f;
        if (tid < 32) {
            for (int i = tid; i < (int)gridDim.x; i += 32) {
                volatile float* vp = (volatile float*)&g_part[i];
                flr += vp[0];
                flp += vp[1];
            }
            #pragma unroll
            for (int o = 16; o > 0; o >>= 1) {
                flr += __shfl_down_sync(FULL, flr, o);
                flp += __shfl_down_sync(FULL, flp, o);
            }
            if (tid == 0) {
                float mlr = flr * inv_nf;
                float mlp = flp * inv_nf;
                out[0] = mlr + 10.0f * mlp;   // LAMBDA_RHOA=1, LAMBDA_PHASE=10
                out[1] = mlr;
                out[2] = mlp;
                g_ticket = 0;                 // reset for next graph replay
            }
        }
    }
}

extern "C" void kernel_launch(void* const* d_in, const int* in_sizes, int n_in,
                              void* d_out, int out_size)
{
    const float* res = (const float*)d_in[0];
    const float* th  = (const float*)d_in[1];
    const float* fr  = (const float*)d_in[2];
    const float* orh = (const float*)d_in[3];
    const float* oph = (const float*)d_in[4];
    int nz = in_sizes[0];
    int nf = in_sizes[2];

    const int threads = 128;               // 4 warps: 1 vector + 3 matrix
    int blocks = (nf + 31) / 32;           // 512 blocks -> ~3.46/SM on 148 SMs
    if (blocks > 512) blocks = 512;

    mt_fused<<<blocks, threads>>>(res, th, fr, orh, oph,
                                  (float*)d_out, nz, nf, 1.0f / (float)nf);
}